// round 4
// baseline (speedup 1.0000x reference)
#include <cuda_runtime.h>
#include <math.h>

#define BATCH 2048
#define STEPS 64
#define HID   64
#define NZv   32
#define INZ   32
#define DOUT  8
#define BT    14
#define NTHR  512
#define NCTA  ((BATCH + BT - 1) / BT)   /* 147 */

// -------- pre-transposed weight scratch (filled by prep_kernel each call) ----
__device__ float g_W0T [65  * 256];   // row k: [Wv0[:,k] | Wc0[:,k]]  (k=0 is the t column)
__device__ float g_W1T [128 * 256];   // row k: [Wv1[:,k] | Wc1[:,k]]
__device__ float g_Wv2T[128 * 64];    // Wv2T[k][o]
__device__ float g_Wc2T[128 * 2048];  // Wc2T[k][n]
__device__ float g_Wi0T[32  * 128];
__device__ float g_Wi1T[128 * 128];
__device__ float g_Wi2T[128 * 64];
__device__ float g_b0  [256];         // [bv0 | bc0]
__device__ float g_b1  [256];         // [bv1 | bc1]
__device__ float g_WrT [64 * 8];      // WrT[h][d]

__global__ void prep_kernel(const float* __restrict__ Wi0, const float* __restrict__ Wi1,
                            const float* __restrict__ Wi2,
                            const float* __restrict__ Wv0, const float* __restrict__ bv0,
                            const float* __restrict__ Wv1, const float* __restrict__ bv1,
                            const float* __restrict__ Wv2,
                            const float* __restrict__ Wc0, const float* __restrict__ bc0,
                            const float* __restrict__ Wc1, const float* __restrict__ bc1,
                            const float* __restrict__ Wc2, const float* __restrict__ Wr) {
    int tid = blockIdx.x * blockDim.x + threadIdx.x;
    int nt  = gridDim.x * blockDim.x;
    for (int i = tid; i < 65 * 256; i += nt) {
        int k = i >> 8, o = i & 255;
        g_W0T[i] = (o < 128) ? Wv0[o * 65 + k] : Wc0[(o - 128) * 65 + k];
    }
    for (int i = tid; i < 128 * 256; i += nt) {
        int k = i >> 8, o = i & 255;
        g_W1T[i] = (o < 128) ? Wv1[o * 128 + k] : Wc1[(o - 128) * 128 + k];
    }
    for (int i = tid; i < 128 * 64; i += nt) {
        int k = i >> 6, o = i & 63;
        g_Wv2T[i] = Wv2[o * 128 + k];
    }
    for (int i = tid; i < 128 * 2048; i += nt) {
        int k = i >> 11, n = i & 2047;
        g_Wc2T[i] = Wc2[n * 128 + k];
    }
    for (int i = tid; i < 32 * 128; i += nt) {
        int k = i >> 7, o = i & 127;
        g_Wi0T[i] = Wi0[o * 32 + k];
    }
    for (int i = tid; i < 128 * 128; i += nt) {
        int k = i >> 7, o = i & 127;
        g_Wi1T[i] = Wi1[o * 128 + k];
    }
    for (int i = tid; i < 128 * 64; i += nt) {
        int k = i >> 6, o = i & 63;
        g_Wi2T[i] = Wi2[o * 128 + k];
    }
    for (int i = tid; i < 256; i += nt) {
        g_b0[i] = (i < 128) ? bv0[i] : bc0[i - 128];
        g_b1[i] = (i < 128) ? bv1[i] : bc1[i - 128];
    }
    for (int i = tid; i < 64 * 8; i += nt) {
        int h = i >> 3, d = i & 7;
        g_WrT[i] = Wr[d * 64 + h];
    }
}

__device__ __forceinline__ float lipswish(float x) {
    // 0.909 * silu(x)
    return 0.909f * x * (1.0f / (1.0f + expf(-x)));
}

__global__ void __launch_bounds__(NTHR, 1) sde_kernel(
    const float* __restrict__ ts, const float* __restrict__ init_noise,
    const float* __restrict__ bm,
    const float* __restrict__ bi0, const float* __restrict__ bi1, const float* __restrict__ bi2,
    const float* __restrict__ scale_v, const float* __restrict__ bv2,
    const float* __restrict__ scale_c, const float* __restrict__ bc2,
    const float* __restrict__ br, float* __restrict__ out)
{
    __shared__ float y_s   [BT][64];       // current state
    __shared__ float ynew_s[BT][64];       // y + drift
    __shared__ float h1_s  [16][256];      // [hv1 | hc1]  (padded rows 14,15)
    __shared__ float h2_s  [16][256];      // [hv2 | hc2]
    __shared__ float diff_s[64][17];       // diffusion increment, [h][b], padded
    __shared__ float bm_s  [16][32];       // per-step noise (reused for init noise)

    const int tid  = threadIdx.x;
    const int b0g  = blockIdx.x * BT;
    int nb = BATCH - b0g; if (nb > BT) nb = BT;
    const float ts0 = ts[0];

    // ---------------- initial MLP: init_noise -> y0 ----------------
    for (int i = tid; i < 16 * 32; i += NTHR) {
        int b = i >> 5, z = i & 31;
        bm_s[b][z] = (b < nb) ? init_noise[(size_t)(b0g + b) * INZ + z] : 0.0f;
    }
    __syncthreads();
    {   // L0: 32 -> 128, relu
        int o = tid & 127, g = tid >> 7;
        float acc[4];
        float bias = bi0[o];
        #pragma unroll
        for (int j = 0; j < 4; j++) acc[j] = bias;
        for (int k = 0; k < 32; k++) {
            float w = g_Wi0T[k * 128 + o];
            #pragma unroll
            for (int j = 0; j < 4; j++) acc[j] = fmaf(w, bm_s[g * 4 + j][k], acc[j]);
        }
        #pragma unroll
        for (int j = 0; j < 4; j++) h1_s[g * 4 + j][o] = fmaxf(acc[j], 0.0f);
    }
    __syncthreads();
    {   // L1: 128 -> 128, relu
        int o = tid & 127, g = tid >> 7;
        float acc[4];
        float bias = bi1[o];
        #pragma unroll
        for (int j = 0; j < 4; j++) acc[j] = bias;
        for (int k = 0; k < 128; k++) {
            float w = g_Wi1T[k * 128 + o];
            #pragma unroll
            for (int j = 0; j < 4; j++) acc[j] = fmaf(w, h1_s[g * 4 + j][k], acc[j]);
        }
        #pragma unroll
        for (int j = 0; j < 4; j++) h2_s[g * 4 + j][o] = fmaxf(acc[j], 0.0f);
    }
    __syncthreads();
    {   // L2: 128 -> 64, identity -> y0
        int o = tid & 63, g = tid >> 6;
        float bias = bi2[o];
        float a0 = bias, a1 = bias;
        for (int k = 0; k < 128; k++) {
            float w = g_Wi2T[k * 64 + o];
            a0 = fmaf(w, h2_s[g * 2 + 0][k], a0);
            a1 = fmaf(w, h2_s[g * 2 + 1][k], a1);
        }
        if (g * 2 + 0 < BT) y_s[g * 2 + 0][o] = a0;
        if (g * 2 + 1 < BT) y_s[g * 2 + 1][o] = a1;
    }
    __syncthreads();

    // ---------------- time scan ----------------
    for (int step = 0; step < STEPS; step++) {
        // stage noise for this step
        for (int i = tid; i < 16 * 32; i += NTHR) {
            int b = i >> 5, z = i & 31;
            bm_s[b][z] = (b < nb)
                ? bm[(size_t)(b0g + b) * (STEPS * NZv) + step * NZv + z] : 0.0f;
        }
        // ---- phase B: layer0 of v & c paths (256 outputs, K=65) ----
        {
            int o = tid & 255, g = tid >> 8, bb = g * 7;
            float tcur = ts0 + (float)step;
            float w0 = g_W0T[o];
            float bias = g_b0[o];
            float acc[7];
            #pragma unroll
            for (int j = 0; j < 7; j++) acc[j] = fmaf(w0, tcur, bias);
            #pragma unroll 2
            for (int k = 0; k < 64; k += 4) {
                float wa = g_W0T[(k + 1) * 256 + o];
                float wb = g_W0T[(k + 2) * 256 + o];
                float wc = g_W0T[(k + 3) * 256 + o];
                float wd = g_W0T[(k + 4) * 256 + o];
                #pragma unroll
                for (int j = 0; j < 7; j++) {
                    float4 a = *(const float4*)&y_s[bb + j][k];
                    acc[j] = fmaf(wa, a.x, acc[j]);
                    acc[j] = fmaf(wb, a.y, acc[j]);
                    acc[j] = fmaf(wc, a.z, acc[j]);
                    acc[j] = fmaf(wd, a.w, acc[j]);
                }
            }
            #pragma unroll
            for (int j = 0; j < 7; j++) h1_s[bb + j][o] = lipswish(acc[j]);
        }
        __syncthreads();
        // ---- phase C: layer1 of v & c paths (256 outputs, K=128) ----
        {
            int o = tid & 255, g = tid >> 8, bb = g * 7;
            int koff = (o < 128) ? 0 : 128;
            float bias = g_b1[o];
            float acc[7];
            #pragma unroll
            for (int j = 0; j < 7; j++) acc[j] = bias;
            #pragma unroll 2
            for (int k = 0; k < 128; k += 4) {
                float wa = g_W1T[(k + 0) * 256 + o];
                float wb = g_W1T[(k + 1) * 256 + o];
                float wc = g_W1T[(k + 2) * 256 + o];
                float wd = g_W1T[(k + 3) * 256 + o];
                #pragma unroll
                for (int j = 0; j < 7; j++) {
                    float4 a = *(const float4*)&h1_s[bb + j][koff + k];
                    acc[j] = fmaf(wa, a.x, acc[j]);
                    acc[j] = fmaf(wb, a.y, acc[j]);
                    acc[j] = fmaf(wc, a.z, acc[j]);
                    acc[j] = fmaf(wd, a.w, acc[j]);
                }
            }
            #pragma unroll
            for (int j = 0; j < 7; j++) h2_s[bb + j][o] = lipswish(acc[j]);
        }
        __syncthreads();
        // ---- phase D: drift head (64 outputs, K=128) -> ynew = y + scale_v*tanh ----
        {
            int o = tid & 63, g = tid >> 6;   // g in 0..7, b = 2g, 2g+1
            float bias = bv2[o];
            float a0 = bias, a1 = bias;
            #pragma unroll 2
            for (int k = 0; k < 128; k += 4) {
                float wa = g_Wv2T[(k + 0) * 64 + o];
                float wb = g_Wv2T[(k + 1) * 64 + o];
                float wc = g_Wv2T[(k + 2) * 64 + o];
                float wd = g_Wv2T[(k + 3) * 64 + o];
                float4 x0 = *(const float4*)&h2_s[g * 2 + 0][k];
                float4 x1 = *(const float4*)&h2_s[g * 2 + 1][k];
                a0 = fmaf(wa, x0.x, a0); a0 = fmaf(wb, x0.y, a0);
                a0 = fmaf(wc, x0.z, a0); a0 = fmaf(wd, x0.w, a0);
                a1 = fmaf(wa, x1.x, a1); a1 = fmaf(wb, x1.y, a1);
                a1 = fmaf(wc, x1.z, a1); a1 = fmaf(wd, x1.w, a1);
            }
            float sv = scale_v[o];
            int bb = g * 2;
            if (bb + 0 < BT) ynew_s[bb + 0][o] = y_s[bb + 0][o] + sv * tanhf(a0);
            if (bb + 1 < BT) ynew_s[bb + 1][o] = y_s[bb + 1][o] + sv * tanhf(a1);
        }
        // ---- phase E: controlled field (2048 outputs, K=128) + NZ contraction ----
        {
            int lane = tid & 31;
            #pragma unroll 1
            for (int it = 0; it < 4; it++) {
                int n = it * 512 + tid;          // h = n>>5 unique per (warp,it); nz = lane
                float sc  = scale_c[n];
                float bco = bc2[n];
                const float* wp = g_Wc2T + n;
                float acc[14];
                #pragma unroll
                for (int b = 0; b < 14; b++) acc[b] = 0.0f;
                #pragma unroll 2
                for (int k = 0; k < 128; k += 4) {
                    float w0 = wp[(k + 0) * 2048];
                    float w1 = wp[(k + 1) * 2048];
                    float w2 = wp[(k + 2) * 2048];
                    float w3 = wp[(k + 3) * 2048];
                    #pragma unroll
                    for (int b = 0; b < 14; b++) {
                        float4 a = *(const float4*)&h2_s[b][128 + k];
                        acc[b] = fmaf(w0, a.x, acc[b]);
                        acc[b] = fmaf(w1, a.y, acc[b]);
                        acc[b] = fmaf(w2, a.z, acc[b]);
                        acc[b] = fmaf(w3, a.w, acc[b]);
                    }
                }
                #pragma unroll
                for (int b = 0; b < 14; b++)
                    acc[b] = sc * tanhf(acc[b] + bco) * bm_s[b][lane];
                #pragma unroll
                for (int off = 16; off > 0; off >>= 1) {
                    #pragma unroll
                    for (int b = 0; b < 14; b++)
                        acc[b] += __shfl_xor_sync(0xffffffffu, acc[b], off);
                }
                if (lane == 0) {
                    int h = n >> 5;
                    #pragma unroll
                    for (int b = 0; b < 14; b++) diff_s[h][b] = acc[b];
                }
            }
        }
        __syncthreads();
        // ---- phase F: y update (FIXED: grid-stride over all BT*64 = 896 > NTHR) ----
        for (int i = tid; i < BT * 64; i += NTHR) {
            int b = i >> 6, h = i & 63;
            y_s[b][h] = ynew_s[b][h] + diff_s[h][b];
        }
        __syncthreads();
        // ---- readout: out[b, step, :] = y @ Wr^T + br ----
        if (tid < BT * DOUT) {
            int b = tid >> 3, d = tid & 7;
            if (b < nb) {
                float acc = br[d];
                #pragma unroll 8
                for (int h = 0; h < 64; h++)
                    acc = fmaf(y_s[b][h], g_WrT[h * 8 + d], acc);
                out[(size_t)(b0g + b) * (STEPS * DOUT) + step * DOUT + d] = acc;
            }
        }
        // next iteration's bm_s write is safe: phase-E reads happened before the
        // post-D/E __syncthreads(); readout only reads y_s.
    }
}

extern "C" void kernel_launch(void* const* d_in, const int* in_sizes, int n_in,
                              void* d_out, int out_size) {
    (void)in_sizes; (void)n_in; (void)out_size;
    const float* ts         = (const float*)d_in[0];
    const float* init_noise = (const float*)d_in[1];
    const float* bm         = (const float*)d_in[2];
    const float* Wi0        = (const float*)d_in[3];
    const float* bi0        = (const float*)d_in[4];
    const float* Wi1        = (const float*)d_in[5];
    const float* bi1        = (const float*)d_in[6];
    const float* Wi2        = (const float*)d_in[7];
    const float* bi2        = (const float*)d_in[8];
    const float* scale_v    = (const float*)d_in[9];
    const float* Wv0        = (const float*)d_in[10];
    const float* bv0        = (const float*)d_in[11];
    const float* Wv1        = (const float*)d_in[12];
    const float* bv1        = (const float*)d_in[13];
    const float* Wv2        = (const float*)d_in[14];
    const float* bv2        = (const float*)d_in[15];
    const float* scale_c    = (const float*)d_in[16];
    const float* Wc0        = (const float*)d_in[17];
    const float* bc0        = (const float*)d_in[18];
    const float* Wc1        = (const float*)d_in[19];
    const float* bc1        = (const float*)d_in[20];
    const float* Wc2        = (const float*)d_in[21];
    const float* bc2        = (const float*)d_in[22];
    const float* Wr         = (const float*)d_in[23];
    const float* br         = (const float*)d_in[24];
    float* out = (float*)d_out;

    prep_kernel<<<256, 256>>>(Wi0, Wi1, Wi2, Wv0, bv0, Wv1, bv1, Wv2,
                              Wc0, bc0, Wc1, bc1, Wc2, Wr);
    sde_kernel<<<NCTA, NTHR>>>(ts, init_noise, bm, bi0, bi1, bi2,
                               scale_v, bv2, scale_c, bc2, br, out);
}

// round 5
// speedup vs baseline: 1.6501x; 1.6501x over previous
#include <cuda_runtime.h>
#include <math.h>

#define BATCH 2048
#define STEPS 64
#define HID   64
#define NZv   32
#define INZ   32
#define DOUT  8
#define BT    14
#define NTHR  512
#define NCTA  ((BATCH + BT - 1) / BT)   /* 147 */

// -------- pre-transposed weight scratch (filled by prep_kernel each call) ----
__device__ float g_W0T [65  * 256];   // row k: [Wv0[:,k] | Wc0[:,k]]  (k=0 is the t column)
__device__ float g_W1T [128 * 256];   // row k: [Wv1[:,k] | Wc1[:,k]]
__device__ float g_Wv2T[128 * 64];    // Wv2T[k][o]
__device__ float g_Wc2T[128 * 2048];  // Wc2T[k][n]  (n contiguous -> LDG.128 per k)
__device__ float g_Wi0T[32  * 128];
__device__ float g_Wi1T[128 * 128];
__device__ float g_Wi2T[128 * 64];
__device__ float g_b0  [256];         // [bv0 | bc0]
__device__ float g_b1  [256];         // [bv1 | bc1]
__device__ float g_WrT [64 * 8];      // WrT[h][d]

__global__ void prep_kernel(const float* __restrict__ Wi0, const float* __restrict__ Wi1,
                            const float* __restrict__ Wi2,
                            const float* __restrict__ Wv0, const float* __restrict__ bv0,
                            const float* __restrict__ Wv1, const float* __restrict__ bv1,
                            const float* __restrict__ Wv2,
                            const float* __restrict__ Wc0, const float* __restrict__ bc0,
                            const float* __restrict__ Wc1, const float* __restrict__ bc1,
                            const float* __restrict__ Wc2, const float* __restrict__ Wr) {
    int tid = blockIdx.x * blockDim.x + threadIdx.x;
    int nt  = gridDim.x * blockDim.x;
    for (int i = tid; i < 65 * 256; i += nt) {
        int k = i >> 8, o = i & 255;
        g_W0T[i] = (o < 128) ? Wv0[o * 65 + k] : Wc0[(o - 128) * 65 + k];
    }
    for (int i = tid; i < 128 * 256; i += nt) {
        int k = i >> 8, o = i & 255;
        g_W1T[i] = (o < 128) ? Wv1[o * 128 + k] : Wc1[(o - 128) * 128 + k];
    }
    for (int i = tid; i < 128 * 64; i += nt) {
        int k = i >> 6, o = i & 63;
        g_Wv2T[i] = Wv2[o * 128 + k];
    }
    for (int i = tid; i < 128 * 2048; i += nt) {
        int k = i >> 11, n = i & 2047;
        g_Wc2T[i] = Wc2[n * 128 + k];
    }
    for (int i = tid; i < 32 * 128; i += nt) {
        int k = i >> 7, o = i & 127;
        g_Wi0T[i] = Wi0[o * 32 + k];
    }
    for (int i = tid; i < 128 * 128; i += nt) {
        int k = i >> 7, o = i & 127;
        g_Wi1T[i] = Wi1[o * 128 + k];
    }
    for (int i = tid; i < 128 * 64; i += nt) {
        int k = i >> 6, o = i & 63;
        g_Wi2T[i] = Wi2[o * 128 + k];
    }
    for (int i = tid; i < 256; i += nt) {
        g_b0[i] = (i < 128) ? bv0[i] : bc0[i - 128];
        g_b1[i] = (i < 128) ? bv1[i] : bc1[i - 128];
    }
    for (int i = tid; i < 64 * 8; i += nt) {
        int h = i >> 3, d = i & 7;
        g_WrT[i] = Wr[d * 64 + h];
    }
}

// fast, accurate-enough transcendentals (abs err ~1e-6)
__device__ __forceinline__ float tanh_fast(float x) {
    float e = __expf(2.0f * x);
    return 1.0f - __fdividef(2.0f, 1.0f + e);
}
__device__ __forceinline__ float lipswish(float x) {
    // 0.909 * x * sigmoid(x)
    return 0.909f * __fdividef(x, 1.0f + __expf(-x));
}

#define PACK_DUP(out, w) \
    asm("mov.b64 %0, {%1, %1};" : "=l"(out) : "r"(__float_as_uint(w)))
#define PACK2(out, lo, hi) \
    asm("mov.b64 %0, {%1, %2};" : "=l"(out) : "r"(__float_as_uint(lo)), "r"(__float_as_uint(hi)))
#define UNPACK2(lo, hi, in) \
    do { unsigned int _ul, _uh; \
         asm("mov.b64 {%0, %1}, %2;" : "=r"(_ul), "=r"(_uh) : "l"(in)); \
         lo = __uint_as_float(_ul); hi = __uint_as_float(_uh); } while (0)
#define FMA2(acc, w2, a2) \
    asm("fma.rn.f32x2 %0, %1, %2, %0;" : "+l"(acc) : "l"(w2), "l"(a2))

__global__ void __launch_bounds__(NTHR, 1) sde_kernel(
    const float* __restrict__ ts, const float* __restrict__ init_noise,
    const float* __restrict__ bm,
    const float* __restrict__ bi0, const float* __restrict__ bi1, const float* __restrict__ bi2,
    const float* __restrict__ scale_v, const float* __restrict__ bv2,
    const float* __restrict__ scale_c, const float* __restrict__ bc2,
    const float* __restrict__ br, float* __restrict__ out)
{
    __shared__ float  y_s   [BT][64];     // current state
    __shared__ float  ynew_s[BT][64];     // y + drift
    __shared__ float  h1_s  [16][256];    // [hv1 | hc1]  (padded rows 14,15)
    __shared__ float  h2v_s [16][128];    // drift-path hidden2 (v half only)
    __shared__ float4 h2q   [64][9];      // c-half hidden2, pair-packed:
                                          // h2q[kk][j] = {A[j][2kk],A[j+7][2kk],A[j][2kk+1],A[j+7][2kk+1]}
    __shared__ float  diff_s[64][17];     // diffusion increment, [h][b], padded
    __shared__ float2 bmp   [32][9];      // noise pairs: bmp[nz][j] = {bm[b=j], bm[b=j+7]}

    const int tid  = threadIdx.x;
    const int b0g  = blockIdx.x * BT;
    int nb = BATCH - b0g; if (nb > BT) nb = BT;
    const float ts0 = ts[0];

    // ---------------- initial MLP: init_noise -> y0 ----------------
    {
        float* nbuf = (float*)bmp;   // reuse as [14][32] staging
        for (int i = tid; i < BT * 32; i += NTHR) {
            int b = i >> 5, z = i & 31;
            nbuf[b * 32 + z] = (b < nb) ? init_noise[(size_t)(b0g + b) * INZ + z] : 0.0f;
        }
        __syncthreads();
        {   // L0: 32 -> 128, relu
            int o = tid & 127, g = tid >> 7;
            float acc[4];
            float bias = bi0[o];
            #pragma unroll
            for (int j = 0; j < 4; j++) acc[j] = bias;
            for (int k = 0; k < 32; k++) {
                float w = g_Wi0T[k * 128 + o];
                #pragma unroll
                for (int j = 0; j < 4; j++) acc[j] = fmaf(w, nbuf[(g * 4 + j) * 32 + k], acc[j]);
            }
            #pragma unroll
            for (int j = 0; j < 4; j++) h1_s[g * 4 + j][o] = fmaxf(acc[j], 0.0f);
        }
        __syncthreads();
        {   // L1: 128 -> 128, relu
            int o = tid & 127, g = tid >> 7;
            float acc[4];
            float bias = bi1[o];
            #pragma unroll
            for (int j = 0; j < 4; j++) acc[j] = bias;
            for (int k = 0; k < 128; k++) {
                float w = g_Wi1T[k * 128 + o];
                #pragma unroll
                for (int j = 0; j < 4; j++) acc[j] = fmaf(w, h1_s[g * 4 + j][k], acc[j]);
            }
            #pragma unroll
            for (int j = 0; j < 4; j++) h2v_s[g * 4 + j][o] = fmaxf(acc[j], 0.0f);
        }
        __syncthreads();
        {   // L2: 128 -> 64, identity -> y0
            int o = tid & 63, g = tid >> 6;
            float bias = bi2[o];
            float a0 = bias, a1 = bias;
            for (int k = 0; k < 128; k++) {
                float w = g_Wi2T[k * 64 + o];
                a0 = fmaf(w, h2v_s[g * 2 + 0][k], a0);
                a1 = fmaf(w, h2v_s[g * 2 + 1][k], a1);
            }
            if (g * 2 + 0 < BT) y_s[g * 2 + 0][o] = a0;
            if (g * 2 + 1 < BT) y_s[g * 2 + 1][o] = a1;
        }
        __syncthreads();
    }

    // ---------------- time scan ----------------
    for (int step = 0; step < STEPS; step++) {
        // stage noise for this step, pre-paired (b, b+7)
        for (int i = tid; i < BT * 32; i += NTHR) {
            int b = i >> 5, z = i & 31;
            float v = (b < nb)
                ? bm[(size_t)(b0g + b) * (STEPS * NZv) + step * NZv + z] : 0.0f;
            int j = (b < 7) ? b : b - 7;
            float* p = (float*)&bmp[z][j];
            p[(b < 7) ? 0 : 1] = v;
        }
        // ---- phase B: layer0 of v & c paths (256 outputs, K=65) ----
        {
            int o = tid & 255, g = tid >> 8, bb = g * 7;
            float tcur = ts0 + (float)step;
            float w0 = g_W0T[o];
            float bias = g_b0[o];
            float acc[7];
            #pragma unroll
            for (int j = 0; j < 7; j++) acc[j] = fmaf(w0, tcur, bias);
            #pragma unroll 2
            for (int k = 0; k < 64; k += 4) {
                float wa = g_W0T[(k + 1) * 256 + o];
                float wb = g_W0T[(k + 2) * 256 + o];
                float wc = g_W0T[(k + 3) * 256 + o];
                float wd = g_W0T[(k + 4) * 256 + o];
                #pragma unroll
                for (int j = 0; j < 7; j++) {
                    float4 a = *(const float4*)&y_s[bb + j][k];
                    acc[j] = fmaf(wa, a.x, acc[j]);
                    acc[j] = fmaf(wb, a.y, acc[j]);
                    acc[j] = fmaf(wc, a.z, acc[j]);
                    acc[j] = fmaf(wd, a.w, acc[j]);
                }
            }
            #pragma unroll
            for (int j = 0; j < 7; j++) h1_s[bb + j][o] = lipswish(acc[j]);
        }
        __syncthreads();
        // ---- phase C: layer1 of v & c paths (256 outputs, K=128) ----
        {
            int o = tid & 255, g = tid >> 8, bb = g * 7;
            int koff = (o < 128) ? 0 : 128;
            float bias = g_b1[o];
            float acc[7];
            #pragma unroll
            for (int j = 0; j < 7; j++) acc[j] = bias;
            #pragma unroll 2
            for (int k = 0; k < 128; k += 4) {
                float wa = g_W1T[(k + 0) * 256 + o];
                float wb = g_W1T[(k + 1) * 256 + o];
                float wc = g_W1T[(k + 2) * 256 + o];
                float wd = g_W1T[(k + 3) * 256 + o];
                #pragma unroll
                for (int j = 0; j < 7; j++) {
                    float4 a = *(const float4*)&h1_s[bb + j][koff + k];
                    acc[j] = fmaf(wa, a.x, acc[j]);
                    acc[j] = fmaf(wb, a.y, acc[j]);
                    acc[j] = fmaf(wc, a.z, acc[j]);
                    acc[j] = fmaf(wd, a.w, acc[j]);
                }
            }
            if (o < 128) {
                #pragma unroll
                for (int j = 0; j < 7; j++) h2v_s[bb + j][o] = lipswish(acc[j]);
            } else {
                // pair-packed write for phase E: component c = 2*(k&1) + g
                int k = o - 128, kk = k >> 1, c = ((k & 1) << 1) + g;
                float* hq = (float*)h2q;
                #pragma unroll
                for (int j = 0; j < 7; j++)
                    hq[(kk * 9 + j) * 4 + c] = lipswish(acc[j]);
            }
        }
        __syncthreads();
        // ---- phase D: drift head (64 outputs, K=128) -> ynew = y + scale_v*tanh ----
        {
            int o = tid & 63, g = tid >> 6;   // g in 0..7, b = 2g, 2g+1
            float bias = bv2[o];
            float a0 = bias, a1 = bias;
            #pragma unroll 2
            for (int k = 0; k < 128; k += 4) {
                float wa = g_Wv2T[(k + 0) * 64 + o];
                float wb = g_Wv2T[(k + 1) * 64 + o];
                float wc = g_Wv2T[(k + 2) * 64 + o];
                float wd = g_Wv2T[(k + 3) * 64 + o];
                float4 x0 = *(const float4*)&h2v_s[g * 2 + 0][k];
                float4 x1 = *(const float4*)&h2v_s[g * 2 + 1][k];
                a0 = fmaf(wa, x0.x, a0); a0 = fmaf(wb, x0.y, a0);
                a0 = fmaf(wc, x0.z, a0); a0 = fmaf(wd, x0.w, a0);
                a1 = fmaf(wa, x1.x, a1); a1 = fmaf(wb, x1.y, a1);
                a1 = fmaf(wc, x1.z, a1); a1 = fmaf(wd, x1.w, a1);
            }
            float sv = scale_v[o];
            int bb = g * 2;
            if (bb + 0 < BT) ynew_s[bb + 0][o] = y_s[bb + 0][o] + sv * tanh_fast(a0);
            if (bb + 1 < BT) ynew_s[bb + 1][o] = y_s[bb + 1][o] + sv * tanh_fast(a1);
        }
        // ---- phase E: controlled field, 4 consecutive n per thread, f32x2 packed ----
        {
            const int n0 = tid << 2;                 // 4*tid
            unsigned long long acc2[4][7];
            #pragma unroll
            for (int ni = 0; ni < 4; ni++)
                #pragma unroll
                for (int j = 0; j < 7; j++) acc2[ni][j] = 0ULL;

            const float4* wb = ((const float4*)g_Wc2T) + tid;   // + k*512 per row
            float4 wA = wb[0];
            float4 wB = wb[512];
            #pragma unroll 1
            for (int kk = 0; kk < 64; kk++) {
                float4 nA, nB;
                if (kk < 63) {
                    nA = wb[(size_t)(2 * kk + 2) * 512];
                    nB = wb[(size_t)(2 * kk + 3) * 512];
                }
                unsigned long long wA2[4], wB2[4];
                PACK_DUP(wA2[0], wA.x); PACK_DUP(wA2[1], wA.y);
                PACK_DUP(wA2[2], wA.z); PACK_DUP(wA2[3], wA.w);
                PACK_DUP(wB2[0], wB.x); PACK_DUP(wB2[1], wB.y);
                PACK_DUP(wB2[2], wB.z); PACK_DUP(wB2[3], wB.w);
                #pragma unroll
                for (int j = 0; j < 7; j++) {
                    float4 a = h2q[kk][j];
                    unsigned long long alo, ahi;
                    PACK2(alo, a.x, a.y);
                    PACK2(ahi, a.z, a.w);
                    FMA2(acc2[0][j], wA2[0], alo); FMA2(acc2[0][j], wB2[0], ahi);
                    FMA2(acc2[1][j], wA2[1], alo); FMA2(acc2[1][j], wB2[1], ahi);
                    FMA2(acc2[2][j], wA2[2], alo); FMA2(acc2[2][j], wB2[2], ahi);
                    FMA2(acc2[3][j], wA2[3], alo); FMA2(acc2[3][j], wB2[3], ahi);
                }
                wA = nA; wB = nB;
            }
            // epilogue: bias + tanh + scale + noise, accumulate over the thread's 4 nz
            float2 s[7];
            #pragma unroll
            for (int j = 0; j < 7; j++) s[j] = make_float2(0.0f, 0.0f);
            const int nzb = (tid & 7) << 2;
            #pragma unroll
            for (int ni = 0; ni < 4; ni++) {
                float sc = scale_c[n0 + ni];
                float bc = bc2[n0 + ni];
                #pragma unroll
                for (int j = 0; j < 7; j++) {
                    float z0, z1;
                    UNPACK2(z0, z1, acc2[ni][j]);
                    float t0 = sc * tanh_fast(z0 + bc);
                    float t1 = sc * tanh_fast(z1 + bc);
                    float2 bmv = bmp[nzb + ni][j];
                    s[j].x = fmaf(t0, bmv.x, s[j].x);
                    s[j].y = fmaf(t1, bmv.y, s[j].y);
                }
            }
            // reduce across the 8-lane group that shares h = tid>>3
            #pragma unroll
            for (int off = 1; off <= 4; off <<= 1) {
                #pragma unroll
                for (int j = 0; j < 7; j++) {
                    s[j].x += __shfl_xor_sync(0xffffffffu, s[j].x, off);
                    s[j].y += __shfl_xor_sync(0xffffffffu, s[j].y, off);
                }
            }
            if ((tid & 7) == 0) {
                int h = tid >> 3;
                #pragma unroll
                for (int j = 0; j < 7; j++) {
                    diff_s[h][j]     = s[j].x;
                    diff_s[h][j + 7] = s[j].y;
                }
            }
        }
        __syncthreads();
        // ---- phase F: y update ----
        for (int i = tid; i < BT * 64; i += NTHR) {
            int b = i >> 6, h = i & 63;
            y_s[b][h] = ynew_s[b][h] + diff_s[h][b];
        }
        __syncthreads();
        // ---- readout: out[b, step, :] = y @ Wr^T + br ----
        if (tid < BT * DOUT) {
            int b = tid >> 3, d = tid & 7;
            if (b < nb) {
                float acc = br[d];
                #pragma unroll 8
                for (int h = 0; h < 64; h++)
                    acc = fmaf(y_s[b][h], g_WrT[h * 8 + d], acc);
                out[(size_t)(b0g + b) * (STEPS * DOUT) + step * DOUT + d] = acc;
            }
        }
    }
}

extern "C" void kernel_launch(void* const* d_in, const int* in_sizes, int n_in,
                              void* d_out, int out_size) {
    (void)in_sizes; (void)n_in; (void)out_size;
    const float* ts         = (const float*)d_in[0];
    const float* init_noise = (const float*)d_in[1];
    const float* bm         = (const float*)d_in[2];
    const float* Wi0        = (const float*)d_in[3];
    const float* bi0        = (const float*)d_in[4];
    const float* Wi1        = (const float*)d_in[5];
    const float* bi1        = (const float*)d_in[6];
    const float* Wi2        = (const float*)d_in[7];
    const float* bi2        = (const float*)d_in[8];
    const float* scale_v    = (const float*)d_in[9];
    const float* Wv0        = (const float*)d_in[10];
    const float* bv0        = (const float*)d_in[11];
    const float* Wv1        = (const float*)d_in[12];
    const float* bv1        = (const float*)d_in[13];
    const float* Wv2        = (const float*)d_in[14];
    const float* bv2        = (const float*)d_in[15];
    const float* scale_c    = (const float*)d_in[16];
    const float* Wc0        = (const float*)d_in[17];
    const float* bc0        = (const float*)d_in[18];
    const float* Wc1        = (const float*)d_in[19];
    const float* bc1        = (const float*)d_in[20];
    const float* Wc2        = (const float*)d_in[21];
    const float* bc2        = (const float*)d_in[22];
    const float* Wr         = (const float*)d_in[23];
    const float* br         = (const float*)d_in[24];
    float* out = (float*)d_out;

    prep_kernel<<<256, 256>>>(Wi0, Wi1, Wi2, Wv0, bv0, Wv1, bv1, Wv2,
                              Wc0, bc0, Wc1, bc1, Wc2, Wr);
    sde_kernel<<<NCTA, NTHR>>>(ts, init_noise, bm, bi0, bi1, bi2,
                               scale_v, bv2, scale_c, bc2, br, out);
}